// round 7
// baseline (speedup 1.0000x reference)
#include <cuda_runtime.h>
#include <cstdint>

// Problem constants
#define B_   64
#define D_   128
#define T_   2048
#define K_   1024
#define N_   (B_ * T_)            // 131072 tokens
#define ND_  (N_ * D_)            // 16777216
#define DECAYF 0.99f
#define EPSF   1e-5f

typedef unsigned long long ull;

// -------- device scratch (no allocations allowed) --------
__device__ float g_counts[K_];
__device__ float g_dw[K_ * D_];
__device__ float g_e2[K_];
__device__ float g_cs[K_];
__device__ float g_losssum;
__device__ float g_embT[D_ * K_];   // transposed codebook: [d][k]

// -------- packed f32x2 helpers (FFMA2 path: 2x fp32 FMA rate on sm_103a) --------
__device__ __forceinline__ ull pack2(float lo, float hi) {
    ull r;
    asm("mov.b64 %0, {%1, %2};" : "=l"(r) : "f"(lo), "f"(hi));
    return r;
}
__device__ __forceinline__ void unpack2(ull v, float& lo, float& hi) {
    asm("mov.b64 {%0, %1}, %2;" : "=f"(lo), "=f"(hi) : "l"(v));
}
__device__ __forceinline__ ull ffma2(ull a, ull b, ull c) {
    ull d;
    asm("fma.rn.f32x2 %0, %1, %2, %3;" : "=l"(d) : "l"(a), "l"(b), "l"(c));
    return d;
}

// -------- cp.async 16B --------
__device__ __forceinline__ void cp_async16(void* smem_dst, const void* gmem_src) {
    unsigned sdst = (unsigned)__cvta_generic_to_shared(smem_dst);
    asm volatile("cp.async.cg.shared.global [%0], [%1], 16;\n" :: "r"(sdst), "l"(gmem_src));
}
__device__ __forceinline__ void cp_async_commit() {
    asm volatile("cp.async.commit_group;\n" ::: "memory");
}
__device__ __forceinline__ void cp_async_wait0() {
    asm volatile("cp.async.wait_group 0;\n" ::: "memory");
}

// -------- zero scratch each launch (graph-replayable) --------
__global__ void k_zero() {
    int i = blockIdx.x * blockDim.x + threadIdx.x;
    if (i < K_ * D_) g_dw[i] = 0.0f;
    if (i < K_)      g_counts[i] = 0.0f;
    if (i == 0)      g_losssum = 0.0f;
}

// -------- |e_k|^2 per code (warp per code) --------
__global__ void k_e2(const float* __restrict__ emb) {
    int w    = (blockIdx.x * blockDim.x + threadIdx.x) >> 5;
    int lane = threadIdx.x & 31;
    for (int k = w; k < K_; k += (gridDim.x * blockDim.x) >> 5) {
        float s = 0.0f;
        const float* row = emb + (size_t)k * D_;
        for (int d = lane; d < D_; d += 32) {
            float v = row[d];
            s += v * v;
        }
        #pragma unroll
        for (int off = 16; off >= 1; off >>= 1)
            s += __shfl_xor_sync(0xffffffffu, s, off);
        if (lane == 0) g_e2[k] = s;
    }
}

// -------- one-time codebook transpose: g_embT[d][k] = emb[k][d] --------
__global__ void k_prep(const float* __restrict__ emb) {
    __shared__ float tile[32][33];
    int k0 = blockIdx.x * 32;
    int d0 = blockIdx.y * 32;
    int lx = threadIdx.x;        // 0..31
    int ly = threadIdx.y;        // 0..7
    #pragma unroll
    for (int r = 0; r < 32; r += 8)
        tile[ly + r][lx] = emb[(size_t)(k0 + ly + r) * D_ + d0 + lx];
    __syncthreads();
    #pragma unroll
    for (int r = 0; r < 32; r += 8)
        g_embT[(size_t)(d0 + ly + r) * K_ + k0 + lx] = tile[lx][ly + r];
}

// -------- main fused kernel --------
// Block: 128 tokens vs all 1024 codes. 512 threads (16 warps; 4/SMSP for latency
// hiding), thread grid 16(ty) x 32(tx). Micro-tile: 8 tokens x 4 codes.
// f32x2 accumulators pack TOKEN pairs (Xs is [d][tok], so consecutive tokens are
// natively packed -> zero A-side MOVs); only the 4 B values are lane-duplicated.
// Codes per thread: {tx*2, tx*2+1, 64+tx*2, 65+tx*2} (stride-32 pairs -> LDS.64
// of the E row is conflict-free).
// Dot accumulation order (d ascending, single chain), xsq reduction (2x64 halves),
// and distance rounding fl(fl(xsq+e2) - 2*dot) are bit-identical to the previous
// passing kernel, so argmin/idx are unchanged.
__global__ __launch_bounds__(512, 1)
void k_main(const float* __restrict__ x, const float* __restrict__ emb,
            float* __restrict__ out, float* __restrict__ idxOut, int writeAux)
{
    extern __shared__ float sm[];
    float* Xs     = sm;                          // [128 d][128 tok]        16384
    float* Es     = Xs + 128 * 128;              // 2 x [128 d][128 codes]  32768
    float* e2all  = Es + 2 * 128 * 128;          // 1024
    float* tokMin = e2all + K_;                  // 128
    int*   tokIdx = (int*)(tokMin + 128);        // 128
    float* red    = (float*)(tokIdx + 128);      // 512
    float* xsqs   = red + 512;                   // 128

    const int tid  = threadIdx.x;
    const int tile = blockIdx.x;
    const int b    = tile >> 4;
    const int t0   = (tile & 15) << 7;

    const float* xbase = x + ((size_t)b * D_) * T_ + t0;

    // ---- kick off E chunk 0 prefetch immediately ----
    {
        #pragma unroll
        for (int u = 0; u < 8; ++u) {
            int q = tid + u * 512;           // 4096 16B units (64KB)
            int d = q >> 5;
            int o = (q & 31) * 4;
            cp_async16(Es + d * 128 + o, g_embT + (size_t)d * K_ + o);
        }
        cp_async_commit();
    }

    // ---- load X tile [d][tok] (coalesced float4) + e2 table ----
    #pragma unroll
    for (int r = 0; r < 8; ++r) {
        int f4 = tid + 512 * r;
        int d  = f4 >> 5;
        int tt = (f4 & 31) * 4;
        float4 v = *reinterpret_cast<const float4*>(xbase + (size_t)d * T_ + tt);
        *reinterpret_cast<float4*>(&Xs[d * 128 + tt]) = v;
    }
    #pragma unroll
    for (int i = tid; i < K_; i += 512) e2all[i] = g_e2[i];
    __syncthreads();

    // ---- per-token |x|^2: IDENTICAL arithmetic to previous passing kernel ----
    if (tid < 256) {
        int t    = tid >> 1;
        int half = tid & 1;
        float s = 0.0f;
        const float* col = &Xs[(half * 64) * 128 + t];
        #pragma unroll 8
        for (int d = 0; d < 64; ++d) {
            float v = col[d * 128];
            s += v * v;
        }
        red[tid] = s;
    }
    __syncthreads();
    if (tid < 128) xsqs[tid] = red[2 * tid] + red[2 * tid + 1];

    const int tx = tid & 31;
    const int ty = tid >> 5;

    float minv[8];
    int   mini[8];
    #pragma unroll
    for (int i = 0; i < 8; ++i) { minv[i] = 3.4e38f; mini[i] = 0; }

    const float* xrow = &Xs[ty * 8];

    for (int ch = 0; ch < 8; ++ch) {
        cp_async_wait0();
        __syncthreads();   // chunk data visible; previous compute done; xsqs ready (iter 0)

        // prefetch next chunk into the other buffer (overlaps with compute below)
        if (ch + 1 < 8) {
            float* nb = Es + ((ch + 1) & 1) * (128 * 128);
            const float* src = g_embT + (ch + 1) * 128;
            #pragma unroll
            for (int u = 0; u < 8; ++u) {
                int q = tid + u * 512;
                int d = q >> 5;
                int o = (q & 31) * 4;
                cp_async16(nb + d * 128 + o, src + (size_t)d * K_ + o);
            }
            cp_async_commit();
        }

        const float* erow = Es + (ch & 1) * (128 * 128) + tx * 2;

        ull acc[4][4];   // [token pair p][code c]
        #pragma unroll
        for (int p = 0; p < 4; ++p)
            #pragma unroll
            for (int c = 0; c < 4; ++c) acc[p][c] = 0ULL;

        #pragma unroll 2
        for (int d = 0; d < 128; ++d) {
            // A: 8 consecutive tokens = 4 native f32x2 pairs (no packing needed)
            const ull* arow = reinterpret_cast<const ull*>(xrow + d * 128);
            ull ap0 = arow[0], ap1 = arow[1], ap2 = arow[2], ap3 = arow[3];
            // B: codes (tx*2, tx*2+1) and (64+tx*2, 65+tx*2) — conflict-free LDS.64
            const ull* brow = reinterpret_cast<const ull*>(erow + d * 128);
            float b0, b1, b2, b3;
            unpack2(brow[0],  b0, b1);
            unpack2(brow[32], b2, b3);
            ull bd0 = pack2(b0, b0), bd1 = pack2(b1, b1);
            ull bd2 = pack2(b2, b2), bd3 = pack2(b3, b3);
            acc[0][0] = ffma2(ap0, bd0, acc[0][0]);
            acc[1][0] = ffma2(ap1, bd0, acc[1][0]);
            acc[2][0] = ffma2(ap2, bd0, acc[2][0]);
            acc[3][0] = ffma2(ap3, bd0, acc[3][0]);
            acc[0][1] = ffma2(ap0, bd1, acc[0][1]);
            acc[1][1] = ffma2(ap1, bd1, acc[1][1]);
            acc[2][1] = ffma2(ap2, bd1, acc[2][1]);
            acc[3][1] = ffma2(ap3, bd1, acc[3][1]);
            acc[0][2] = ffma2(ap0, bd2, acc[0][2]);
            acc[1][2] = ffma2(ap1, bd2, acc[1][2]);
            acc[2][2] = ffma2(ap2, bd2, acc[2][2]);
            acc[3][2] = ffma2(ap3, bd2, acc[3][2]);
            acc[0][3] = ffma2(ap0, bd3, acc[0][3]);
            acc[1][3] = ffma2(ap1, bd3, acc[1][3]);
            acc[2][3] = ffma2(ap2, bd3, acc[2][3]);
            acc[3][3] = ffma2(ap3, bd3, acc[3][3]);
        }

        // ---- fold chunk into running argmin with reference-matching rounding ----
        // Per-token code visit order ascending (c = 0..3 maps to ascending code
        // index), strict-< keeps the lowest index on rounded ties.
        #pragma unroll
        for (int c = 0; c < 4; ++c) {
            int code = ch * 128 + (c >> 1) * 64 + tx * 2 + (c & 1);
            float e2 = e2all[code];
            #pragma unroll
            for (int p = 0; p < 4; ++p) {
                float s0, s1;
                unpack2(acc[p][c], s0, s1);
                float xq0 = xsqs[ty * 8 + 2 * p];
                float xq1 = xsqs[ty * 8 + 2 * p + 1];
                float d0 = (xq0 + e2) - 2.0f * s0;
                float d1 = (xq1 + e2) - 2.0f * s1;
                if (d0 < minv[2 * p])     { minv[2 * p]     = d0; mini[2 * p]     = code; }
                if (d1 < minv[2 * p + 1]) { minv[2 * p + 1] = d1; mini[2 * p + 1] = code; }
            }
        }
    }

    // ---- cross-lane argmin reduction over the full warp; ties -> smaller idx ----
    #pragma unroll
    for (int i = 0; i < 8; ++i) {
        #pragma unroll
        for (int off = 16; off >= 1; off >>= 1) {
            float v2 = __shfl_xor_sync(0xffffffffu, minv[i], off);
            int   i2 = __shfl_xor_sync(0xffffffffu, mini[i], off);
            if (v2 < minv[i] || (v2 == minv[i] && i2 < mini[i])) {
                minv[i] = v2; mini[i] = i2;
            }
        }
        if (tx == 0) {
            tokMin[ty * 8 + i] = minv[i];
            tokIdx[ty * 8 + i] = mini[i];
        }
    }
    __syncthreads();

    // ---- epilogue: idx out + histogram ----
    const int n0 = b * T_ + t0;
    if (tid < 128) {
        if (writeAux) idxOut[n0 + tid] = (float)tokIdx[tid];
        atomicAdd(&g_counts[tokIdx[tid]], 1.0f);
    }

    // ---- loss partial: sum of min distances (== sum |x - q|^2) ----
    {
        red[tid] = (tid < 128) ? tokMin[tid] : 0.0f;
        __syncthreads();
        #pragma unroll
        for (int s = 256; s > 0; s >>= 1) {
            if (tid < s) red[tid] += red[tid + s];
            __syncthreads();
        }
        if (tid == 0) atomicAdd(&g_losssum, red[0]);
    }

    // ---- dw scatter: g_dw[idx[t], :] += x[t, :]  (vectorized red.v4, no return) ----
    {
        int t = tid >> 2;
        int q = tid & 3;
        int code = tokIdx[t];
        float* dst = &g_dw[(size_t)code * D_ + q * 32];
        const float* src = &Xs[(q * 32) * 128 + t];
        #pragma unroll
        for (int d = 0; d < 32; d += 4) {
            float v0 = src[(d + 0) * 128];
            float v1 = src[(d + 1) * 128];
            float v2 = src[(d + 2) * 128];
            float v3 = src[(d + 3) * 128];
            asm volatile("red.global.add.v4.f32 [%0], {%1, %2, %3, %4};"
                         :: "l"(dst + d), "f"(v0), "f"(v1), "f"(v2), "f"(v3)
                         : "memory");
        }
    }

    // ---- quantized output: out[b][d][t] = E[idx[t]][d] (coalesced writes, L2-hot gathers) ----
    {
        float* obase = out + ((size_t)b * D_) * T_ + t0;
        #pragma unroll 4
        for (int q = tid; q < 128 * D_; q += 512) {
            int d = q >> 7;
            int t = q & 127;
            obase[(size_t)d * T_ + t] = emb[(size_t)tokIdx[t] * D_ + d];
        }
    }
}

// -------- finalize A: n = sum(avg_cs), Laplace-smoothed cluster sizes, losses --------
__global__ void k_finalA(const float* __restrict__ hidC, float* __restrict__ lossOut, int writeAux) {
    __shared__ float red[K_];
    int k = threadIdx.x;
    const float onemd = 1.0f - DECAYF;
    float c   = g_counts[k];
    float h   = hidC[k];
    float hid = h - (h - c) * onemd;
    float avg = hid / onemd;               // denom = 1 - DECAY^1
    red[k] = avg;
    __syncthreads();
    for (int s = 512; s > 0; s >>= 1) {
        if (k < s) red[k] += red[k + s];
        __syncthreads();
    }
    float n  = red[0];
    float cs = (avg + EPSF) / (n + (float)K_ * EPSF) * n;
    g_cs[k] = cs;
    if (k == 0 && writeAux) {
        float M = g_losssum / (float)ND_;
        lossOut[0] = 0.25f * M;   // commit
        lossOut[1] = M;           // vq
    }
}

// -------- finalize B: new_embeddings = avg_dw / cs --------
__global__ void k_finalB(const float* __restrict__ hidDW, float* __restrict__ neOut) {
    int i = blockIdx.x * blockDim.x + threadIdx.x;
    if (i >= K_ * D_) return;
    const float onemd = 1.0f - DECAYF;
    float dwv = g_dw[i];
    float h   = hidDW[i];
    float hid = h - (h - dwv) * onemd;
    float avg = hid / onemd;
    neOut[i] = avg / g_cs[i >> 7];
}

extern "C" void kernel_launch(void* const* d_in, const int* in_sizes, int n_in,
                              void* d_out, int out_size) {
    const float* x     = (const float*)d_in[0];   // [64,128,2048]
    const float* emb   = (const float*)d_in[1];   // [1024,128]
    const float* hidDW = (const float*)d_in[2];   // [1024,128]
    const float* hidC  = (const float*)d_in[3];   // [1024]

    float* out = (float*)d_out;
    // Expected packing: out | loss_commit | loss_vq | idx | new_embeddings
    int writeAux = (out_size >= (ND_ + 2 + N_ + K_ * D_)) ? 1 : 0;
    float* lossOut = out + ND_;
    float* idxOut  = lossOut + 2;
    float* neOut   = idxOut + N_;

    const size_t smem =
        (size_t)(128 * 128 + 2 * 128 * 128 + K_ + 128 + 128 + 512 + 128) * 4;
    cudaFuncSetAttribute(k_main, cudaFuncAttributeMaxDynamicSharedMemorySize, (int)smem);

    k_zero<<<512, 256>>>();
    k_e2<<<32, 256>>>(emb);
    {
        dim3 g(K_ / 32, D_ / 32), blk(32, 8);
        k_prep<<<g, blk>>>(emb);
    }
    k_main<<<1024, 512, smem>>>(x, emb, out, idxOut, writeAux);
    k_finalA<<<1, 1024>>>(hidC, lossOut, writeAux);
    if (writeAux) k_finalB<<<512, 256>>>(hidDW, neOut);
}

// round 13
// speedup vs baseline: 1.7999x; 1.7999x over previous
#include <cuda_runtime.h>
#include <cstdint>

// Problem constants
#define B_   64
#define D_   128
#define T_   2048
#define K_   1024
#define N_   (B_ * T_)            // 131072 tokens
#define ND_  (N_ * D_)            // 16777216
#define DECAYF 0.99f
#define EPSF   1e-5f

#define MARGIN 0.06f              // screen margin (bf16 dot err sigma ~2e-3 -> ~13 sigma on 2*dot)

#define PB 272                    // bf16 tile row pitch in BYTES (136 bf16) - conflict-free ldmatrix

// smem layout (float offsets; all 16B-aligned)
#define OFF_XS   0                // fp32 X tile [128 d][128 tok]   16384
#define OFF_XBF  16384            // bf16 A tile [128 tok][136 d]    8704
#define OFF_B0   25088            // bf16 B buf0 [128 code][136 d]   8704
#define OFF_B1   33792            // bf16 B buf1                     8704
#define OFF_E2   42496            // 1024
#define OFF_XSQ  43520            // 128
#define OFF_TMIN 43648            // 128
#define OFF_TIDX 43776            // 128
#define OFF_RED  43904            // 512
#define OFF_CD   44416            // candD [128 tok][32]             4096
#define OFF_CI   48512            // candI shorts [128 tok][32]      2048
#define SMEM_FLOATS 50560         // 202240 bytes

// -------- device scratch (no allocations allowed) --------
__device__ float g_counts[K_];
__device__ float g_dw[K_ * D_];
__device__ float g_e2[K_];
__device__ float g_cs[K_];
__device__ float g_losssum;
__device__ unsigned g_embBf[K_ * 64];   // bf16 codebook [code][64 x bf16x2], d-contiguous

// -------- helpers --------
__device__ __forceinline__ uint32_t pack_bf16(float hi, float lo) {
    uint32_t v;
    asm("cvt.rn.bf16x2.f32 %0, %1, %2;" : "=r"(v) : "f"(hi), "f"(lo));
    return v;
}
__device__ __forceinline__ void ldmatrix_x4(uint32_t* r, uint32_t addr) {
    asm volatile("ldmatrix.sync.aligned.m8n8.x4.shared.b16 {%0,%1,%2,%3}, [%4];"
                 : "=r"(r[0]), "=r"(r[1]), "=r"(r[2]), "=r"(r[3]) : "r"(addr));
}
__device__ __forceinline__ void ldmatrix_x2(uint32_t* r, uint32_t addr) {
    asm volatile("ldmatrix.sync.aligned.m8n8.x2.shared.b16 {%0,%1}, [%2];"
                 : "=r"(r[0]), "=r"(r[1]) : "r"(addr));
}
__device__ __forceinline__ void mma16816(float* c, const uint32_t* a, const uint32_t* b) {
    asm volatile("mma.sync.aligned.m16n8k16.row.col.f32.bf16.bf16.f32 "
                 "{%0,%1,%2,%3}, {%4,%5,%6,%7}, {%8,%9}, {%0,%1,%2,%3};"
                 : "+f"(c[0]), "+f"(c[1]), "+f"(c[2]), "+f"(c[3])
                 : "r"(a[0]), "r"(a[1]), "r"(a[2]), "r"(a[3]), "r"(b[0]), "r"(b[1]));
}
__device__ __forceinline__ void cp_async16(uint32_t smem_dst, const void* gmem_src) {
    asm volatile("cp.async.cg.shared.global [%0], [%1], 16;" :: "r"(smem_dst), "l"(gmem_src));
}
// sorted top-4 insert (strict < keeps earliest/lowest code on equal values)
__device__ __forceinline__ void ins4(float dd, int idx, float* m, int* mi) {
    if (dd < m[3]) {
        if (dd < m[2]) {
            m[3] = m[2]; mi[3] = mi[2];
            if (dd < m[1]) {
                m[2] = m[1]; mi[2] = mi[1];
                if (dd < m[0]) { m[1] = m[0]; mi[1] = mi[0]; m[0] = dd; mi[0] = idx; }
                else           { m[1] = dd; mi[1] = idx; }
            } else { m[2] = dd; mi[2] = idx; }
        } else { m[3] = dd; mi[3] = idx; }
    }
}

// -------- zero scratch each launch (graph-replayable) --------
__global__ void k_zero() {
    int i = blockIdx.x * blockDim.x + threadIdx.x;
    if (i < K_ * D_) g_dw[i] = 0.0f;
    if (i < K_)      g_counts[i] = 0.0f;
    if (i == 0)      g_losssum = 0.0f;
}

// -------- |e_k|^2 per code (IDENTICAL to passing kernel) --------
__global__ void k_e2(const float* __restrict__ emb) {
    int w    = (blockIdx.x * blockDim.x + threadIdx.x) >> 5;
    int lane = threadIdx.x & 31;
    for (int k = w; k < K_; k += (gridDim.x * blockDim.x) >> 5) {
        float s = 0.0f;
        const float* row = emb + (size_t)k * D_;
        for (int d = lane; d < D_; d += 32) {
            float v = row[d];
            s += v * v;
        }
        #pragma unroll
        for (int off = 16; off >= 1; off >>= 1)
            s += __shfl_xor_sync(0xffffffffu, s, off);
        if (lane == 0) g_e2[k] = s;
    }
}

// -------- prep: codebook -> bf16 [code][d] (d-contiguous bf16x2) --------
__global__ void k_prepB(const float* __restrict__ emb) {
    int i0 = blockIdx.x * 256 + threadIdx.x;
    #pragma unroll
    for (int u = 0; u < 4; ++u) {
        int i = i0 + u * 16384;          // 0..65535
        int p = i & 63;                  // d-pair
        int k = i >> 6;                  // code
        float lo = emb[k * 128 + 2 * p];
        float hi = emb[k * 128 + 2 * p + 1];
        g_embBf[k * 64 + p] = pack_bf16(hi, lo);
    }
}

// -------- B chunk cp.async: 128 codes x 256B, smem pitch 272B --------
__device__ __forceinline__ void load_chunk(uint32_t bbuf_u32, int ch, int tid) {
    const char* src0 = (const char*)g_embBf + (size_t)ch * 128 * 256;
    #pragma unroll
    for (int u = 0; u < 4; ++u) {
        int q  = tid + u * 512;          // 0..2047 16B units
        int cl = q >> 4;                 // code local 0..127
        int un = q & 15;
        cp_async16(bbuf_u32 + cl * PB + un * 16, src0 + (size_t)cl * 256 + un * 16);
    }
}

// -------- main fused kernel: bf16 mma.sync screen + exact fp32 refine + epilogue --------
__global__ __launch_bounds__(512, 1)
void k_main(const float* __restrict__ x, const float* __restrict__ emb,
            float* __restrict__ out, float* __restrict__ idxOut, int writeAux)
{
    extern __shared__ float sm[];
    float* Xs     = sm + OFF_XS;
    float* e2all  = sm + OFF_E2;
    float* xsqs   = sm + OFF_XSQ;
    float* tokMin = sm + OFF_TMIN;
    int*   tokIdx = (int*)(sm + OFF_TIDX);
    float* red    = sm + OFF_RED;
    float* candD  = sm + OFF_CD;
    short* candI  = (short*)(sm + OFF_CI);

    const int tid  = threadIdx.x;
    const int wid  = tid >> 5;
    const int lane = tid & 31;
    const uint32_t smem_u32 = (uint32_t)__cvta_generic_to_shared(sm);
    const uint32_t xbf_u32  = smem_u32 + OFF_XBF * 4;
    const uint32_t b0_u32   = smem_u32 + OFF_B0 * 4;
    const uint32_t b1_u32   = smem_u32 + OFF_B1 * 4;

    const int tile = blockIdx.x;
    const int b    = tile >> 4;
    const int t0   = (tile & 15) << 7;
    const float* xbase = x + ((size_t)b * D_) * T_ + t0;

    // prefetch B chunks 0 and 1
    load_chunk(b0_u32, 0, tid);
    asm volatile("cp.async.commit_group;" ::: "memory");
    load_chunk(b1_u32, 1, tid);
    asm volatile("cp.async.commit_group;" ::: "memory");

    // load X tile [d][tok] fp32 + e2 table
    #pragma unroll
    for (int r = 0; r < 8; ++r) {
        int f4 = tid + 512 * r;
        int d  = f4 >> 5;
        int tt = (f4 & 31) * 4;
        float4 v = *reinterpret_cast<const float4*>(xbase + (size_t)d * T_ + tt);
        *reinterpret_cast<float4*>(&Xs[d * 128 + tt]) = v;
    }
    #pragma unroll
    for (int i = tid; i < K_; i += 512) e2all[i] = g_e2[i];
    __syncthreads();

    // per-token |x|^2 partials (IDENTICAL arithmetic to passing kernel)
    if (tid < 256) {
        int t    = tid >> 1;
        int half = tid & 1;
        float s = 0.0f;
        const float* col = &Xs[(half * 64) * 128 + t];
        #pragma unroll 8
        for (int d = 0; d < 64; ++d) {
            float v = col[d * 128];
            s += v * v;
        }
        red[tid] = s;
    }
    // bf16 A tile: Xbf[t][d], pitch 272B
    for (int i = tid; i < 8192; i += 512) {
        int t = i & 127;
        int p = i >> 7;            // d-pair 0..63
        float lo = Xs[(2 * p) * 128 + t];
        float hi = Xs[(2 * p + 1) * 128 + t];
        *(uint32_t*)((char*)sm + (size_t)OFF_XBF * 4 + t * PB + p * 4) = pack_bf16(hi, lo);
    }
    __syncthreads();
    if (tid < 128) xsqs[tid] = red[2 * tid] + red[2 * tid + 1];
    __syncthreads();

    // ---- per-warp tiling: warp = token group (16) x code half (64) ----
    const int tg = wid >> 1;       // 0..7
    const int h  = wid & 1;        // 0..1

    // preload A fragments (8 k-steps x 4 regs)
    uint32_t afr[8][4];
    {
        int mI = lane >> 3;
        uint32_t aaddr = xbf_u32 + (uint32_t)(tg * 16 + (mI & 1) * 8 + (lane & 7)) * PB
                                 + (uint32_t)(mI >> 1) * 16;
        #pragma unroll
        for (int kk = 0; kk < 8; ++kk)
            ldmatrix_x4(afr[kk], aaddr + kk * 32);
    }

    const float xq0 = xsqs[tg * 16 + (lane >> 2)];
    const float xq1 = xsqs[tg * 16 + (lane >> 2) + 8];

    // top-4 per lane per token-row
    float m0[4], m1[4];
    int   i0[4], i1[4];
    #pragma unroll
    for (int j = 0; j < 4; ++j) { m0[j] = 3.4e38f; m1[j] = 3.4e38f; i0[j] = 0; i1[j] = 0; }

    const uint32_t bline = (uint32_t)((lane & 7) * PB + ((lane >> 3) & 1) * 16);

    for (int ch = 0; ch < 8; ++ch) {
        asm volatile("cp.async.wait_group 1;" ::: "memory");
        __syncthreads();    // chunk ch ready; previous compute done (buffers stable)

        const uint32_t bbase = ((ch & 1) ? b1_u32 : b0_u32) + (uint32_t)(h * 64) * PB;

        for (int tl = 0; tl < 8; ++tl) {
            const uint32_t btile = bbase + (uint32_t)(tl * 8) * PB + bline;
            float acc[4] = {0.f, 0.f, 0.f, 0.f};
            #pragma unroll
            for (int kk = 0; kk < 8; ++kk) {
                uint32_t bfr[2];
                ldmatrix_x2(bfr, btile + kk * 32);
                mma16816(acc, afr[kk], bfr);
            }
            int gcode = ch * 128 + h * 64 + tl * 8 + 2 * (lane & 3);
            float e20 = e2all[gcode];
            float e21 = e2all[gcode + 1];
            float d00 = (xq0 + e20) - 2.0f * acc[0];
            float d01 = (xq0 + e21) - 2.0f * acc[1];
            float d10 = (xq1 + e20) - 2.0f * acc[2];
            float d11 = (xq1 + e21) - 2.0f * acc[3];
            ins4(d00, gcode,     m0, i0);
            ins4(d01, gcode + 1, m0, i0);
            ins4(d10, gcode,     m1, i1);
            ins4(d11, gcode + 1, m1, i1);
        }

        __syncthreads();    // compute done; safe to refill buffer
        if (ch + 2 < 8) {
            load_chunk((ch & 1) ? b1_u32 : b0_u32, ch + 2, tid);
            asm volatile("cp.async.commit_group;" ::: "memory");
        }
    }

    // dump candidates: 32 entries per token (8 lanes x top-4)
    {
        int tokA = tg * 16 + (lane >> 2);
        int base = (h * 4 + (lane & 3)) * 4;
        #pragma unroll
        for (int j = 0; j < 4; ++j) {
            candD[tokA * 32 + base + j] = m0[j];
            candI[tokA * 32 + base + j] = (short)i0[j];
            candD[(tokA + 8) * 32 + base + j] = m1[j];
            candI[(tokA + 8) * 32 + base + j] = (short)i1[j];
        }
    }
    __syncthreads();

    // ---- exact fp32 refinement (same rounding chain as passing kernel) ----
    if (tid < 128) {
        int t = tid;
        float xsq = xsqs[t];
        float mn = 3.4e38f;
        #pragma unroll
        for (int s = 0; s < 32; ++s) {
            float v = candD[t * 32 + s];
            if (v < mn) mn = v;
        }
        float best = 3.4e38f;
        int bestIdx = 0x7fffffff;
        for (int s = 0; s < 32; ++s) {
            if (candD[t * 32 + s] >= mn + MARGIN) continue;
            int code = candI[t * 32 + s];
            const float* er = emb + (size_t)code * D_;
            float dot = 0.0f;
            #pragma unroll 8
            for (int d = 0; d < 128; d += 4) {
                float4 e4 = *reinterpret_cast<const float4*>(er + d);
                dot += Xs[(d + 0) * 128 + t] * e4.x;
                dot += Xs[(d + 1) * 128 + t] * e4.y;
                dot += Xs[(d + 2) * 128 + t] * e4.z;
                dot += Xs[(d + 3) * 128 + t] * e4.w;
            }
            float dist = (xsq + e2all[code]) - 2.0f * dot;
            if (dist < best || (dist == best && code < bestIdx)) { best = dist; bestIdx = code; }
        }
        tokMin[t] = best;
        tokIdx[t] = bestIdx;
    }
    __syncthreads();

    // ---- epilogue: idx out + histogram ----
    const int n0 = b * T_ + t0;
    if (tid < 128) {
        if (writeAux) idxOut[n0 + tid] = (float)tokIdx[tid];
        atomicAdd(&g_counts[tokIdx[tid]], 1.0f);
    }

    // ---- loss partial: sum of min distances ----
    {
        red[tid] = (tid < 128) ? tokMin[tid] : 0.0f;
        __syncthreads();
        #pragma unroll
        for (int s = 256; s > 0; s >>= 1) {
            if (tid < s) red[tid] += red[tid + s];
            __syncthreads();
        }
        if (tid == 0) atomicAdd(&g_losssum, red[0]);
    }

    // ---- dw scatter: g_dw[idx[t], :] += x[t, :]  (red.v4, no return) ----
    {
        int t = tid >> 2;
        int q = tid & 3;
        int code = tokIdx[t];
        float* dst = &g_dw[(size_t)code * D_ + q * 32];
        const float* src = &Xs[(q * 32) * 128 + t];
        #pragma unroll
        for (int d = 0; d < 32; d += 4) {
            float v0 = src[(d + 0) * 128];
            float v1 = src[(d + 1) * 128];
            float v2 = src[(d + 2) * 128];
            float v3 = src[(d + 3) * 128];
            asm volatile("red.global.add.v4.f32 [%0], {%1, %2, %3, %4};"
                         :: "l"(dst + d), "f"(v0), "f"(v1), "f"(v2), "f"(v3)
                         : "memory");
        }
    }

    // ---- quantized output: out[b][d][t] = E[idx[t]][d] ----
    {
        float* obase = out + ((size_t)b * D_) * T_ + t0;
        #pragma unroll 4
        for (int q = tid; q < 128 * D_; q += 512) {
            int d = q >> 7;
            int t = q & 127;
            obase[(size_t)d * T_ + t] = emb[(size_t)tokIdx[t] * D_ + d];
        }
    }
}

// -------- finalize A --------
__global__ void k_finalA(const float* __restrict__ hidC, float* __restrict__ lossOut, int writeAux) {
    __shared__ float red[K_];
    int k = threadIdx.x;
    const float onemd = 1.0f - DECAYF;
    float c   = g_counts[k];
    float h   = hidC[k];
    float hid = h - (h - c) * onemd;
    float avg = hid / onemd;
    red[k] = avg;
    __syncthreads();
    for (int s = 512; s > 0; s >>= 1) {
        if (k < s) red[k] += red[k + s];
        __syncthreads();
    }
    float n  = red[0];
    float cs = (avg + EPSF) / (n + (float)K_ * EPSF) * n;
    g_cs[k] = cs;
    if (k == 0 && writeAux) {
        float M = g_losssum / (float)ND_;
        lossOut[0] = 0.25f * M;
        lossOut[1] = M;
    }
}

// -------- finalize B --------
__global__ void k_finalB(const float* __restrict__ hidDW, float* __restrict__ neOut) {
    int i = blockIdx.x * blockDim.x + threadIdx.x;
    if (i >= K_ * D_) return;
    const float onemd = 1.0f - DECAYF;
    float dwv = g_dw[i];
    float h   = hidDW[i];
    float hid = h - (h - dwv) * onemd;
    float avg = hid / onemd;
    neOut[i] = avg / g_cs[i >> 7];
}

extern "C" void kernel_launch(void* const* d_in, const int* in_sizes, int n_in,
                              void* d_out, int out_size) {
    const float* x     = (const float*)d_in[0];   // [64,128,2048]
    const float* emb   = (const float*)d_in[1];   // [1024,128]
    const float* hidDW = (const float*)d_in[2];   // [1024,128]
    const float* hidC  = (const float*)d_in[3];   // [1024]

    float* out = (float*)d_out;
    int writeAux = (out_size >= (ND_ + 2 + N_ + K_ * D_)) ? 1 : 0;
    float* lossOut = out + ND_;
    float* idxOut  = lossOut + 2;
    float* neOut   = idxOut + N_;

    const size_t smem = (size_t)SMEM_FLOATS * 4;
    cudaFuncSetAttribute(k_main, cudaFuncAttributeMaxDynamicSharedMemorySize, (int)smem);

    k_zero<<<512, 256>>>();
    k_e2<<<32, 256>>>(emb);
    k_prepB<<<64, 256>>>(emb);
    k_main<<<1024, 512, smem>>>(x, emb, out, idxOut, writeAux);
    k_finalA<<<1, 1024>>>(hidC, lossOut, writeAux);
    if (writeAux) k_finalB<<<512, 256>>>(hidDW, neOut);
}

// round 14
// speedup vs baseline: 1.8239x; 1.0133x over previous
#include <cuda_runtime.h>
#include <cstdint>

// Problem constants
#define B_   64
#define D_   128
#define T_   2048
#define K_   1024
#define N_   (B_ * T_)            // 131072 tokens
#define ND_  (N_ * D_)            // 16777216
#define DECAYF 0.99f
#define EPSF   1e-5f

#define MARGIN 0.06f              // screen margin (bf16 dot err sigma ~2e-3 -> ~13 sigma on 2*dot)
#define NC    48                  // candidates per token (16 streams x top-3)

#define PB 272                    // bf16 tile row pitch in BYTES (136 bf16) - conflict-free ldmatrix

// smem layout (float offsets; all 16B-aligned)
#define OFF_XS   0                // fp32 X tile [128 d][128 tok]   16384
#define OFF_XBF  16384            // bf16 A tile [128 tok][136 d]    8704
#define OFF_B0   25088            // bf16 B buf0 [128 code][136 d]   8704
#define OFF_B1   33792            // bf16 B buf1                     8704
#define OFF_E2   42496            // 1024
#define OFF_XSQ  43520            // 128
#define OFF_TMIN 43648            // 128
#define OFF_TIDX 43776            // 128
#define OFF_RED  43904            // 512
#define OFF_CD   44416            // candD [128 tok][48]             6144
#define OFF_CI   50560            // candI shorts [128 tok][48]      3072
#define SMEM_FLOATS 53632         // 214528 bytes

// -------- device scratch (no allocations allowed) --------
__device__ float g_counts[K_];
__device__ float g_dw[K_ * D_];
__device__ float g_e2[K_];
__device__ float g_cs[K_];
__device__ float g_losssum;
__device__ unsigned g_embBf[K_ * 64];   // bf16 codebook [code][64 x bf16x2], d-contiguous

// -------- helpers --------
__device__ __forceinline__ uint32_t pack_bf16(float hi, float lo) {
    uint32_t v;
    asm("cvt.rn.bf16x2.f32 %0, %1, %2;" : "=r"(v) : "f"(hi), "f"(lo));
    return v;
}
__device__ __forceinline__ void ldmatrix_x4(uint32_t* r, uint32_t addr) {
    asm volatile("ldmatrix.sync.aligned.m8n8.x4.shared.b16 {%0,%1,%2,%3}, [%4];"
                 : "=r"(r[0]), "=r"(r[1]), "=r"(r[2]), "=r"(r[3]) : "r"(addr));
}
__device__ __forceinline__ void mma16816(float* c, const uint32_t* a, const uint32_t* b) {
    asm volatile("mma.sync.aligned.m16n8k16.row.col.f32.bf16.bf16.f32 "
                 "{%0,%1,%2,%3}, {%4,%5,%6,%7}, {%8,%9}, {%0,%1,%2,%3};"
                 : "+f"(c[0]), "+f"(c[1]), "+f"(c[2]), "+f"(c[3])
                 : "r"(a[0]), "r"(a[1]), "r"(a[2]), "r"(a[3]), "r"(b[0]), "r"(b[1]));
}
__device__ __forceinline__ void cp_async16(uint32_t smem_dst, const void* gmem_src) {
    asm volatile("cp.async.cg.shared.global [%0], [%1], 16;" :: "r"(smem_dst), "l"(gmem_src));
}
// top-3 insert, guarded: common path is one compare (strict < keeps earliest code on ties)
__device__ __forceinline__ void ins3(float dd, int code, float* m, int* mi) {
    if (dd < m[2]) {
        if (dd < m[1]) {
            m[2] = m[1]; mi[2] = mi[1];
            if (dd < m[0]) { m[1] = m[0]; mi[1] = mi[0]; m[0] = dd; mi[0] = code; }
            else           { m[1] = dd; mi[1] = code; }
        } else { m[2] = dd; mi[2] = code; }
    }
}

// -------- zero scratch each launch (graph-replayable) --------
__global__ void k_zero() {
    int i = blockIdx.x * blockDim.x + threadIdx.x;
    if (i < K_ * D_) g_dw[i] = 0.0f;
    if (i < K_)      g_counts[i] = 0.0f;
    if (i == 0)      g_losssum = 0.0f;
}

// -------- |e_k|^2 per code (IDENTICAL to passing kernel) --------
__global__ void k_e2(const float* __restrict__ emb) {
    int w    = (blockIdx.x * blockDim.x + threadIdx.x) >> 5;
    int lane = threadIdx.x & 31;
    for (int k = w; k < K_; k += (gridDim.x * blockDim.x) >> 5) {
        float s = 0.0f;
        const float* row = emb + (size_t)k * D_;
        for (int d = lane; d < D_; d += 32) {
            float v = row[d];
            s += v * v;
        }
        #pragma unroll
        for (int off = 16; off >= 1; off >>= 1)
            s += __shfl_xor_sync(0xffffffffu, s, off);
        if (lane == 0) g_e2[k] = s;
    }
}

// -------- prep: codebook -> bf16 [code][d] (d-contiguous bf16x2) --------
__global__ void k_prepB(const float* __restrict__ emb) {
    int i0 = blockIdx.x * 256 + threadIdx.x;
    #pragma unroll
    for (int u = 0; u < 4; ++u) {
        int i = i0 + u * 16384;          // 0..65535
        int p = i & 63;                  // d-pair
        int k = i >> 6;                  // code
        float lo = emb[k * 128 + 2 * p];
        float hi = emb[k * 128 + 2 * p + 1];
        g_embBf[k * 64 + p] = pack_bf16(hi, lo);
    }
}

// -------- B chunk cp.async: 128 codes x 256B, smem pitch 272B --------
__device__ __forceinline__ void load_chunk(uint32_t bbuf_u32, int ch, int tid) {
    const char* src0 = (const char*)g_embBf + (size_t)ch * 128 * 256;
    #pragma unroll
    for (int u = 0; u < 4; ++u) {
        int q  = tid + u * 512;          // 0..2047 16B units
        int cl = q >> 4;                 // code local 0..127
        int un = q & 15;
        cp_async16(bbuf_u32 + cl * PB + un * 16, src0 + (size_t)cl * 256 + un * 16);
    }
}

// -------- main fused kernel: bf16 mma.sync screen + exact fp32 refine + epilogue --------
// Warp tiling: warp = (32-token group) x (32-code quarter). 16 warps cover
// 128 tok x 128 codes per chunk. Per token: 16 streams (4 quarters x 4 lanes),
// each covering 64 codes with a guarded top-3 -> 48 candidates/token.
__global__ __launch_bounds__(512, 1)
void k_main(const float* __restrict__ x, const float* __restrict__ emb,
            float* __restrict__ out, float* __restrict__ idxOut, int writeAux)
{
    extern __shared__ float sm[];
    float* Xs     = sm + OFF_XS;
    float* e2all  = sm + OFF_E2;
    float* xsqs   = sm + OFF_XSQ;
    float* tokMin = sm + OFF_TMIN;
    int*   tokIdx = (int*)(sm + OFF_TIDX);
    float* red    = sm + OFF_RED;
    float* candD  = sm + OFF_CD;
    short* candI  = (short*)(sm + OFF_CI);

    const int tid  = threadIdx.x;
    const int wid  = tid >> 5;
    const int lane = tid & 31;
    const uint32_t smem_u32 = (uint32_t)__cvta_generic_to_shared(sm);
    const uint32_t xbf_u32  = smem_u32 + OFF_XBF * 4;
    const uint32_t b0_u32   = smem_u32 + OFF_B0 * 4;
    const uint32_t b1_u32   = smem_u32 + OFF_B1 * 4;

    const int tile = blockIdx.x;
    const int b    = tile >> 4;
    const int t0   = (tile & 15) << 7;
    const float* xbase = x + ((size_t)b * D_) * T_ + t0;

    // prefetch B chunks 0 and 1
    load_chunk(b0_u32, 0, tid);
    asm volatile("cp.async.commit_group;" ::: "memory");
    load_chunk(b1_u32, 1, tid);
    asm volatile("cp.async.commit_group;" ::: "memory");

    // load X tile [d][tok] fp32 + e2 table
    #pragma unroll
    for (int r = 0; r < 8; ++r) {
        int f4 = tid + 512 * r;
        int d  = f4 >> 5;
        int tt = (f4 & 31) * 4;
        float4 v = *reinterpret_cast<const float4*>(xbase + (size_t)d * T_ + tt);
        *reinterpret_cast<float4*>(&Xs[d * 128 + tt]) = v;
    }
    #pragma unroll
    for (int i = tid; i < K_; i += 512) e2all[i] = g_e2[i];
    __syncthreads();

    // per-token |x|^2 partials (IDENTICAL arithmetic to passing kernel)
    if (tid < 256) {
        int t    = tid >> 1;
        int half = tid & 1;
        float s = 0.0f;
        const float* col = &Xs[(half * 64) * 128 + t];
        #pragma unroll 8
        for (int d = 0; d < 64; ++d) {
            float v = col[d * 128];
            s += v * v;
        }
        red[tid] = s;
    }
    // bf16 A tile: Xbf[t][d], pitch 272B
    for (int i = tid; i < 8192; i += 512) {
        int t = i & 127;
        int p = i >> 7;            // d-pair 0..63
        float lo = Xs[(2 * p) * 128 + t];
        float hi = Xs[(2 * p + 1) * 128 + t];
        *(uint32_t*)((char*)sm + (size_t)OFF_XBF * 4 + t * PB + p * 4) = pack_bf16(hi, lo);
    }
    __syncthreads();
    if (tid < 128) xsqs[tid] = red[2 * tid] + red[2 * tid + 1];
    __syncthreads();

    // ---- per-warp tiling: warp = 32-token group x 32-code quarter ----
    const int tg = wid >> 2;       // 0..3  (tokens tg*32 .. tg*32+31)
    const int q  = wid & 3;        // 0..3  (codes q*32 .. q*32+31 of each chunk)

    // preload A fragments: 2 x 16-token groups x 8 k-steps x 4 regs
    uint32_t afr0[8][4], afr1[8][4];
    {
        int mI = lane >> 3;
        uint32_t abase = xbf_u32 + (uint32_t)(tg * 32 + (mI & 1) * 8 + (lane & 7)) * PB
                                 + (uint32_t)(mI >> 1) * 16;
        #pragma unroll
        for (int kk = 0; kk < 8; ++kk) ldmatrix_x4(afr0[kk], abase + kk * 32);
        #pragma unroll
        for (int kk = 0; kk < 8; ++kk) ldmatrix_x4(afr1[kk], abase + 16 * PB + kk * 32);
    }

    const int rowb = tg * 32 + (lane >> 2);
    const float xq0 = xsqs[rowb];
    const float xq1 = xsqs[rowb + 8];
    const float xq2 = xsqs[rowb + 16];
    const float xq3 = xsqs[rowb + 24];

    // top-3 per stream: streams = 4 token-rows owned by this lane
    float m[4][3];
    int   mi[4][3];
    #pragma unroll
    for (int s = 0; s < 4; ++s)
        #pragma unroll
        for (int j = 0; j < 3; ++j) { m[s][j] = 3.4e38f; mi[s][j] = 0; }

    const uint32_t bline = (uint32_t)((lane & 7) * PB + (lane >> 3) * 16);

    for (int ch = 0; ch < 8; ++ch) {
        asm volatile("cp.async.wait_group 1;" ::: "memory");
        __syncthreads();    // chunk ch ready; previous compute done (buffers stable)

        const uint32_t bq = ((ch & 1) ? b1_u32 : b0_u32) + (uint32_t)(q * 32) * PB;

        #pragma unroll 1
        for (int nt = 0; nt < 4; ++nt) {
            const uint32_t btile = bq + (uint32_t)(nt * 8) * PB + bline;
            // B frags: k=0..127 for 8 codes -> 16 regs via 4 ldmatrix.x4
            uint32_t bfr[16];
            #pragma unroll
            for (int kg = 0; kg < 4; ++kg)
                ldmatrix_x4(&bfr[kg * 4], btile + kg * 64);

            float acc0[4] = {0.f, 0.f, 0.f, 0.f};
            float acc1[4] = {0.f, 0.f, 0.f, 0.f};
            #pragma unroll
            for (int kk = 0; kk < 8; ++kk) {
                mma16816(acc0, afr0[kk], &bfr[kk * 2]);
                mma16816(acc1, afr1[kk], &bfr[kk * 2]);
            }

            int c0 = ch * 128 + q * 32 + nt * 8 + 2 * (lane & 3);
            float e20 = e2all[c0];
            float e21 = e2all[c0 + 1];
            ins3((xq0 + e20) - 2.0f * acc0[0], c0,     m[0], mi[0]);
            ins3((xq0 + e21) - 2.0f * acc0[1], c0 + 1, m[0], mi[0]);
            ins3((xq1 + e20) - 2.0f * acc0[2], c0,     m[1], mi[1]);
            ins3((xq1 + e21) - 2.0f * acc0[3], c0 + 1, m[1], mi[1]);
            ins3((xq2 + e20) - 2.0f * acc1[0], c0,     m[2], mi[2]);
            ins3((xq2 + e21) - 2.0f * acc1[1], c0 + 1, m[2], mi[2]);
            ins3((xq3 + e20) - 2.0f * acc1[2], c0,     m[3], mi[3]);
            ins3((xq3 + e21) - 2.0f * acc1[3], c0 + 1, m[3], mi[3]);
        }

        __syncthreads();    // compute done; safe to refill buffer
        if (ch + 2 < 8) {
            load_chunk((ch & 1) ? b1_u32 : b0_u32, ch + 2, tid);
            asm volatile("cp.async.commit_group;" ::: "memory");
        }
    }

    // dump candidates: 48 entries per token (16 streams x top-3)
    {
        int sbase = (q * 4 + (lane & 3)) * 3;
        #pragma unroll
        for (int s = 0; s < 4; ++s) {
            int t = rowb + s * 8;
            #pragma unroll
            for (int j = 0; j < 3; ++j) {
                candD[t * NC + sbase + j] = m[s][j];
                candI[t * NC + sbase + j] = (short)mi[s][j];
            }
        }
    }
    __syncthreads();

    // ---- exact fp32 refinement (same rounding chain as passing kernel) ----
    if (tid < 128) {
        int t = tid;
        float xsq = xsqs[t];
        float mn = 3.4e38f;
        #pragma unroll
        for (int s = 0; s < NC; ++s) {
            float v = candD[t * NC + s];
            if (v < mn) mn = v;
        }
        float best = 3.4e38f;
        int bestIdx = 0x7fffffff;
        for (int s = 0; s < NC; ++s) {
            if (candD[t * NC + s] >= mn + MARGIN) continue;
            int code = candI[t * NC + s];
            const float* er = emb + (size_t)code * D_;
            float dot = 0.0f;
            #pragma unroll 8
            for (int d = 0; d < 128; d += 4) {
                float4 e4 = *reinterpret_cast<const float4*>(er + d);
                dot += Xs[(d + 0) * 128 + t] * e4.x;
                dot += Xs[(d + 1) * 128 + t] * e4.y;
                dot += Xs[(d + 2) * 128 + t] * e4.z;
                dot += Xs[(d + 3) * 128 + t] * e4.w;
            }
            float dist = (xsq + e2all[code]) - 2.0f * dot;
            if (dist < best || (dist == best && code < bestIdx)) { best = dist; bestIdx = code; }
        }
        tokMin[t] = best;
        tokIdx[t] = bestIdx;
    }
    __syncthreads();

    // ---- epilogue: idx out + histogram ----
    const int n0 = b * T_ + t0;
    if (tid < 128) {
        if (writeAux) idxOut[n0 + tid] = (float)tokIdx[tid];
        atomicAdd(&g_counts[tokIdx[tid]], 1.0f);
    }

    // ---- loss partial: sum of min distances ----
    {
        red[tid] = (tid < 128) ? tokMin[tid] : 0.0f;
        __syncthreads();
        #pragma unroll
        for (int s = 256; s > 0; s >>= 1) {
            if (tid < s) red[tid] += red[tid + s];
            __syncthreads();
        }
        if (tid == 0) atomicAdd(&g_losssum, red[0]);
    }

    // ---- dw scatter: g_dw[idx[t], :] += x[t, :]  (red.v4, no return) ----
    {
        int t = tid >> 2;
        int qq = tid & 3;
        int code = tokIdx[t];
        float* dst = &g_dw[(size_t)code * D_ + qq * 32];
        const float* src = &Xs[(qq * 32) * 128 + t];
        #pragma unroll
        for (int d = 0; d < 32; d += 4) {
            float v0 = src[(d + 0) * 128];
            float v1 = src[(d + 1) * 128];
            float v2 = src[(d + 2) * 128];
            float v3 = src[(d + 3) * 128];
            asm volatile("red.global.add.v4.f32 [%0], {%1, %2, %3, %4};"
                         :: "l"(dst + d), "f"(v0), "f"(v1), "f"(v2), "f"(v3)
                         : "memory");
        }
    }

    // ---- quantized output: out[b][d][t] = E[idx[t]][d] ----
    {
        float* obase = out + ((size_t)b * D_) * T_ + t0;
        #pragma unroll 4
        for (int qq = tid; qq < 128 * D_; qq += 512) {
            int d = qq >> 7;
            int t = qq & 127;
            obase[(size_t)d * T_ + t] = emb[(size_t)tokIdx[t] * D_ + d];
        }
    }
}

// -------- finalize A --------
__global__ void k_finalA(const float* __restrict__ hidC, float* __restrict__ lossOut, int writeAux) {
    __shared__ float red[K_];
    int k = threadIdx.x;
    const float onemd = 1.0f - DECAYF;
    float c   = g_counts[k];
    float h   = hidC[k];
    float hid = h - (h - c) * onemd;
    float avg = hid / onemd;
    red[k] = avg;
    __syncthreads();
    for (int s = 512; s > 0; s >>= 1) {
        if (k < s) red[k] += red[k + s];
        __syncthreads();
    }
    float n  = red[0];
    float cs = (avg + EPSF) / (n + (float)K_ * EPSF) * n;
    g_cs[k] = cs;
    if (k == 0 && writeAux) {
        float M = g_losssum / (float)ND_;
        lossOut[0] = 0.25f * M;
        lossOut[1] = M;
    }
}

// -------- finalize B --------
__global__ void k_finalB(const float* __restrict__ hidDW, float* __restrict__ neOut) {
    int i = blockIdx.x * blockDim.x + threadIdx.x;
    if (i >= K_ * D_) return;
    const float onemd = 1.0f - DECAYF;
    float dwv = g_dw[i];
    float h   = hidDW[i];
    float hid = h - (h - dwv) * onemd;
    float avg = hid / onemd;
    neOut[i] = avg / g_cs[i >> 7];
}

extern "C" void kernel_launch(void* const* d_in, const int* in_sizes, int n_in,
                              void* d_out, int out_size) {
    const float* x     = (const float*)d_in[0];   // [64,128,2048]
    const float* emb   = (const float*)d_in[1];   // [1024,128]
    const float* hidDW = (const float*)d_in[2];   // [1024,128]
    const float* hidC  = (const float*)d_in[3];   // [1024]

    float* out = (float*)d_out;
    int writeAux = (out_size >= (ND_ + 2 + N_ + K_ * D_)) ? 1 : 0;
    float* lossOut = out + ND_;
    float* idxOut  = lossOut + 2;
    float* neOut   = idxOut + N_;

    const size_t smem = (size_t)SMEM_FLOATS * 4;
    cudaFuncSetAttribute(k_main, cudaFuncAttributeMaxDynamicSharedMemorySize, (int)smem);

    k_zero<<<512, 256>>>();
    k_e2<<<32, 256>>>(emb);
    k_prepB<<<64, 256>>>(emb);
    k_main<<<1024, 512, smem>>>(x, emb, out, idxOut, writeAux);
    k_finalA<<<1, 1024>>>(hidC, lossOut, writeAux);
    if (writeAux) k_finalB<<<512, 256>>>(hidDW, neOut);
}